// round 16
// baseline (speedup 1.0000x reference)
#include <cuda_runtime.h>
#include <cuda_fp16.h>
#include <cstdint>
#include <cstddef>

typedef __half h16;

#define BDIM 16384
#define D1   1536
#define D2   3072
#define DH   512
#define DOUT 6

// ---------------- scratch (static device memory; no allocations) ----------------
static constexpr size_t SZ_X   = (size_t)BDIM * D1;
static constexpr size_t SZ_H   = (size_t)BDIM * DH;
static constexpr size_t SZ_WGE = (size_t)D1 * D1;
static constexpr size_t SZ_WGI = (size_t)D2 * D1;
static constexpr size_t SZ_W1  = (size_t)D1 * DH;
static constexpr size_t SZ_W2  = (size_t)DH * DH;

static constexpr size_t O_X   = 0;
static constexpr size_t O_GE  = O_X  + SZ_X;
static constexpr size_t O_GI  = O_GE + SZ_X;
static constexpr size_t O_H1  = O_GI + SZ_X;
static constexpr size_t O_H2  = O_H1 + SZ_H;
static constexpr size_t O_WGE = O_H2 + SZ_H;
static constexpr size_t O_WGI = O_WGE + SZ_WGE;
static constexpr size_t O_W1  = O_WGI + SZ_WGI;
static constexpr size_t O_W2  = O_W1 + SZ_W1;
static constexpr size_t SCRATCH_TOTAL = O_W2 + SZ_W2;

__device__ __align__(1024) h16 g_scratch[SCRATCH_TOTAL];

// ---------------- ptx helpers ----------------
__device__ __forceinline__ uint32_t smem_u32(const void* p) {
    uint32_t a;
    asm("{ .reg .u64 t; cvta.to.shared.u64 t, %1; cvt.u32.u64 %0, t; }" : "=r"(a) : "l"(p));
    return a;
}

__device__ __forceinline__ void cp16(uint32_t dst, const void* src) {
    asm volatile("cp.async.cg.shared.global [%0], [%1], 16;" :: "r"(dst), "l"(src) : "memory");
}

__device__ __forceinline__ void ldmx4(uint32_t* r, uint32_t addr) {
    asm volatile("ldmatrix.sync.aligned.m8n8.x4.shared.b16 {%0,%1,%2,%3}, [%4];"
        : "=r"(r[0]), "=r"(r[1]), "=r"(r[2]), "=r"(r[3]) : "r"(addr));
}

__device__ __forceinline__ void mma16816(float* c, const uint32_t* a, const uint32_t* b) {
    asm volatile(
        "mma.sync.aligned.m16n8k16.row.col.f32.f16.f16.f32 "
        "{%0,%1,%2,%3},{%4,%5,%6,%7},{%8,%9},{%0,%1,%2,%3};\n"
        : "+f"(c[0]), "+f"(c[1]), "+f"(c[2]), "+f"(c[3])
        : "r"(a[0]), "r"(a[1]), "r"(a[2]), "r"(a[3]),
          "r"(b[0]), "r"(b[1]));
}

// ---------------- prep kernels ----------------
// fp32 -> fp16, 8 floats per thread: 2x LDG.128 -> 1x STG.128
__global__ void cvt_kernel8(const float4* __restrict__ src,
                            uint4* __restrict__ dst, size_t n8) {
    size_t stride = (size_t)gridDim.x * blockDim.x;
    for (size_t i = (size_t)blockIdx.x * blockDim.x + threadIdx.x; i < n8; i += stride) {
        float4 a = src[2 * i];
        float4 b = src[2 * i + 1];
        __half2 h0 = __floats2half2_rn(a.x, a.y);
        __half2 h1 = __floats2half2_rn(a.z, a.w);
        __half2 h2 = __floats2half2_rn(b.x, b.y);
        __half2 h3 = __floats2half2_rn(b.z, b.w);
        uint4 o;
        o.x = *(uint32_t*)&h0; o.y = *(uint32_t*)&h1;
        o.z = *(uint32_t*)&h2; o.w = *(uint32_t*)&h3;
        dst[i] = o;
    }
}

// tiled transpose + optional mask + fp16: w [K][N] -> t [N][K]; mask [N][K].
// Write phase: each thread emits half2 (two consecutive k) -> 4B coalesced stores.
template<bool MASKED>
__global__ void prep_T(const float* __restrict__ w, const float* __restrict__ mask,
                       h16* __restrict__ t, int Kd, int Nd) {
    __shared__ float tl[32][33];
    const int k0 = blockIdx.x * 32, n0 = blockIdx.y * 32;
    const int tx = threadIdx.x, ty = threadIdx.y;  // 32 x 8
#pragma unroll
    for (int i = 0; i < 32; i += 8)
        tl[ty + i][tx] = w[(size_t)(k0 + ty + i) * Nd + (n0 + tx)];
    __syncthreads();
    // remap 256 threads: wtx 0..15 selects k-pair, wty 0..15 selects n row
    const int tid = ty * 32 + tx;
    const int wtx = tid & 15;        // k pair index
    const int wty = tid >> 4;        // 0..15
#pragma unroll
    for (int h = 0; h < 2; h++) {
        const int n = n0 + wty + h * 16;
        const int k = k0 + 2 * wtx;
        float v0 = tl[2 * wtx][wty + h * 16];
        float v1 = tl[2 * wtx + 1][wty + h * 16];
        const size_t idx = (size_t)n * Kd + k;
        if (MASKED) {
            float2 m = *(const float2*)&mask[idx];
            v0 *= m.x; v1 *= m.y;
        }
        *(__half2*)&t[idx] = __floats2half2_rn(v0, v1);
    }
}

// ---------------- mma.sync GEMM: C = A * B^T(+concat) + bias (opt relu), fp16 ----------------
// R11-proven config: CTA 128x128, 256 thr (8 warps), warp tile 64x32,
// BK=64 (128B swizzled rows), 3-stage cp.async (1 barrier/stage), 2 CTAs/SM.
template<int CBM, int CBN, int THREADS, int WM, int WN, bool RELU, bool CONCAT>
__global__ __launch_bounds__(THREADS, 2)
void gemm_hmma(const h16* __restrict__ A, const h16* __restrict__ A2,
               int ksplit,
               const h16* __restrict__ Bt,  // [N][K]
               const float* __restrict__ bias,
               h16* __restrict__ O,
               int N, int K)
{
    constexpr int WARPS_N = CBN / WN;
    constexpr int NI  = WM / 16;
    constexpr int NJ  = WN / 8;
    constexpr int NJP = WN / 16;
    constexpr int ABYTES = CBM * 128;
    constexpr int BBYTES = CBN * 128;
    constexpr int STAGEB = ABYTES + BBYTES;
    constexpr int ACH = CBM * 8;
    constexpr int BCH = CBN * 8;

    extern __shared__ __align__(1024) char smem[];
    const uint32_t sb = smem_u32(smem);

    const int tid  = threadIdx.x;
    const int lane = tid & 31;
    const int warp = tid >> 5;
    const int wm = warp / WARPS_N;
    const int wn = warp % WARPS_N;
    const int blockN = blockIdx.x * CBN;
    const int blockM = blockIdx.y * CBM;

    // ldmatrix lane decomposition
    const int q = lane >> 3;
    const int m8 = lane & 7;
    const int qrA = q & 1;
    const int qcA = q >> 1;
    const int qrB = q >> 1;
    const int qcB = q & 1;

    uint32_t rA[NI], xA[NI];
#pragma unroll
    for (int i = 0; i < NI; i++) {
        int row = wm * WM + i * 16 + qrA * 8 + m8;
        rA[i] = (uint32_t)row * 128u;
        xA[i] = (uint32_t)(row & 7);
    }
    uint32_t rB[NJP], xB[NJP];
#pragma unroll
    for (int jp = 0; jp < NJP; jp++) {
        int row = wn * WN + jp * 16 + qrB * 8 + m8;
        rB[jp] = (uint32_t)row * 128u;
        xB[jp] = (uint32_t)(row & 7);
    }

    float acc[NI][NJ][4];
#pragma unroll
    for (int i = 0; i < NI; i++)
#pragma unroll
        for (int j = 0; j < NJ; j++)
#pragma unroll
            for (int r = 0; r < 4; r++) acc[i][j][r] = 0.f;

    const int S = K / 64;

    auto do_load = [&](int s) {
        const int k0 = s * 64;
        const h16* a;
        size_t lda;
        if (CONCAT && k0 >= ksplit) {
            lda = (size_t)(K - ksplit);
            a = A2 + (size_t)blockM * lda + (k0 - ksplit);
        } else {
            lda = CONCAT ? (size_t)ksplit : (size_t)K;
            a = A + (size_t)blockM * lda + k0;
        }
        const h16* b = Bt + (size_t)blockN * K + k0;
        const uint32_t buf = sb + (uint32_t)(s % 3) * STAGEB;
#pragma unroll 1
        for (int c = tid; c < ACH; c += THREADS) {
            const int row = c >> 3;
            const int col = c & 7;
            const uint32_t soff = (uint32_t)row * 128u + (uint32_t)((col ^ (row & 7)) * 16);
            cp16(buf + soff, (const char*)(a + (size_t)row * lda) + col * 16);
        }
#pragma unroll 1
        for (int c = tid; c < BCH; c += THREADS) {
            const int row = c >> 3;
            const int col = c & 7;
            const uint32_t soff = (uint32_t)row * 128u + (uint32_t)((col ^ (row & 7)) * 16);
            cp16(buf + ABYTES + soff, (const char*)(b + (size_t)row * K) + col * 16);
        }
    };

    do_load(0);
    asm volatile("cp.async.commit_group;" ::: "memory");
    if (S > 1) {
        do_load(1);
        asm volatile("cp.async.commit_group;" ::: "memory");
    }

    for (int s = 0; s < S; s++) {
        if (s < S - 1) asm volatile("cp.async.wait_group 1;" ::: "memory");
        else           asm volatile("cp.async.wait_group 0;" ::: "memory");
        __syncthreads();   // single barrier per stage (3-stage ring)

        if (s + 2 < S) {
            do_load(s + 2);
            asm volatile("cp.async.commit_group;" ::: "memory");
        }

        const uint32_t buf = sb + (uint32_t)(s % 3) * STAGEB;
        const uint32_t bA = buf;
        const uint32_t bB = buf + ABYTES;

#pragma unroll
        for (int ks = 0; ks < 4; ks++) {
            const uint32_t cA = (uint32_t)(ks * 2 + qcA);
            const uint32_t cB = (uint32_t)(ks * 2 + qcB);
            uint32_t af[NI][4], bf[NJP][4];
#pragma unroll
            for (int i = 0; i < NI; i++)
                ldmx4(af[i], bA + rA[i] + ((cA ^ xA[i]) << 4));
#pragma unroll
            for (int jp = 0; jp < NJP; jp++)
                ldmx4(bf[jp], bB + rB[jp] + ((cB ^ xB[jp]) << 4));
#pragma unroll
            for (int j = 0; j < NJ; j++)
#pragma unroll
                for (int i = 0; i < NI; i++)
                    mma16816(acc[i][j], af[i], &bf[j >> 1][(j & 1) * 2]);
        }
    }

    // ---- epilogue: bias, optional relu, fp16 store
    const int g  = lane >> 2;
    const int tg = lane & 3;
#pragma unroll
    for (int i = 0; i < NI; i++) {
#pragma unroll
        for (int j = 0; j < NJ; j++) {
            int row0 = blockM + wm * WM + i * 16 + g;
            int col  = blockN + wn * WN + j * 8 + tg * 2;
            float b0 = bias[col], b1 = bias[col + 1];
#pragma unroll
            for (int h = 0; h < 2; h++) {
                int row = row0 + h * 8;
                float v0 = acc[i][j][h * 2 + 0] + b0;
                float v1 = acc[i][j][h * 2 + 1] + b1;
                if (RELU) { v0 = fmaxf(v0, 0.f); v1 = fmaxf(v1, 0.f); }
                *(__half2*)&O[(size_t)row * N + col] = __floats2half2_rn(v0, v1);
            }
        }
    }
}

// ---------------- final layer: [B,512] x [512,6] + bias, relu (fp32) ----------------
__global__ void final_kernel(const h16* __restrict__ hh,
                             const float* __restrict__ w3, const float* __restrict__ b3,
                             float* __restrict__ out)
{
    int warpId = (int)((blockIdx.x * (size_t)blockDim.x + threadIdx.x) >> 5);
    int lane = threadIdx.x & 31;
    if (warpId >= BDIM) return;
    const h16* ph = hh + (size_t)warpId * DH;
    float acc[6] = {0.f, 0.f, 0.f, 0.f, 0.f, 0.f};
    for (int k = lane; k < DH; k += 32) {
        float h = __half2float(ph[k]);
#pragma unroll
        for (int n = 0; n < 6; n++) acc[n] += h * w3[k * 6 + n];
    }
#pragma unroll
    for (int n = 0; n < 6; n++)
#pragma unroll
        for (int off = 16; off; off >>= 1)
            acc[n] += __shfl_xor_sync(0xffffffffu, acc[n], off);
    if (lane == 0) {
#pragma unroll
        for (int n = 0; n < 6; n++)
            out[(size_t)warpId * 6 + n] = fmaxf(acc[n] + b3[n], 0.f);
    }
}

// ---------------- launch ----------------
// All GEMMs: CTA 128x128, 256 thr, warp 64x32; smem 3*32KB=96KB, 2 CTAs/SM (R11 config)
#define SMEM_TILE (3 * (128 * 128 + 128 * 128))

extern "C" void kernel_launch(void* const* d_in, const int* in_sizes, int n_in,
                              void* d_out, int out_size)
{
    const float* x        = (const float*)d_in[0];
    const float* gpe_mask = (const float*)d_in[1];
    const float* gpe_w    = (const float*)d_in[2];
    const float* gpe_b    = (const float*)d_in[3];
    const float* gpi_mask = (const float*)d_in[4];
    const float* gpi_w    = (const float*)d_in[5];
    const float* gpi_b    = (const float*)d_in[6];
    const float* w1       = (const float*)d_in[7];
    const float* b1       = (const float*)d_in[8];
    const float* w2       = (const float*)d_in[9];
    const float* b2       = (const float*)d_in[10];
    const float* w3       = (const float*)d_in[11];
    const float* b3       = (const float*)d_in[12];
    float* out = (float*)d_out;

    h16* s = nullptr;
    cudaGetSymbolAddress((void**)&s, g_scratch);

    h16 *xc = s + O_X;
    h16 *ge = s + O_GE, *gi = s + O_GI;
    h16 *h1 = s + O_H1, *h2 = s + O_H2;
    h16 *wge = s + O_WGE, *wgi = s + O_WGI;
    h16 *w1c = s + O_W1, *w2c = s + O_W2;

    auto kBig1 = gemm_hmma<128, 128, 256, 64, 32, false, false>;
    auto kBig2 = gemm_hmma<128, 128, 256, 64, 32, false, true>;
    auto kSm   = gemm_hmma<128, 128, 256, 64, 32, true, false>;

    cudaFuncSetAttribute(kBig1, cudaFuncAttributeMaxDynamicSharedMemorySize, SMEM_TILE);
    cudaFuncSetAttribute(kBig2, cudaFuncAttributeMaxDynamicSharedMemorySize, SMEM_TILE);
    cudaFuncSetAttribute(kSm,   cudaFuncAttributeMaxDynamicSharedMemorySize, SMEM_TILE);

    // Launch order keeps the ncu window on big GEMMs.
    cvt_kernel8<<<4096, 256>>>((const float4*)x, (uint4*)xc, SZ_X / 8);
    prep_T<true><<<dim3(D1 / 32, D1 / 32), dim3(32, 8)>>>(gpe_w, gpe_mask, wge, D1, D1);
    prep_T<true><<<dim3(D2 / 32, D1 / 32), dim3(32, 8)>>>(gpi_w, gpi_mask, wgi, D2, D1);
    // layer 1: gpe = x @ Wgpe + b        [B,1536] x [1536,1536]
    kBig1<<<dim3(D1 / 128, BDIM / 128), 256, SMEM_TILE>>>(
        xc, nullptr, D1, wge, gpe_b, ge, D1, D1);
    // layer 2: gpi = [x, gpe] @ Wgpi + b [B,3072] x [3072,1536] (concat fused)
    kBig2<<<dim3(D1 / 128, BDIM / 128), 256, SMEM_TILE>>>(
        xc, ge, D1, wgi, gpi_b, gi, D1, D2);
    prep_T<false><<<dim3(D1 / 32, DH / 32), dim3(32, 8)>>>(w1, nullptr, w1c, D1, DH);
    prep_T<false><<<dim3(DH / 32, DH / 32), dim3(32, 8)>>>(w2, nullptr, w2c, DH, DH);
    // layer 3: h1 = relu(gpi @ w1 + b1)  [B,1536] x [1536,512]
    kSm<<<dim3(DH / 128, BDIM / 128), 256, SMEM_TILE>>>(
        gi, nullptr, D1, w1c, b1, h1, DH, D1);
    // layer 4: h2 = relu(h1 @ w2 + b2)   [B,512] x [512,512]
    kSm<<<dim3(DH / 128, BDIM / 128), 256, SMEM_TILE>>>(
        h1, nullptr, DH, w2c, b2, h2, DH, DH);
    // layer 5: out = relu(h2 @ w3 + b3)  [B,512] x [512,6]
    final_kernel<<<(BDIM * 32) / 256, 256>>>(h2, w3, b3, out);
}

// round 17
// speedup vs baseline: 1.0978x; 1.0978x over previous
#include <cuda_runtime.h>
#include <cuda_fp16.h>
#include <cstdint>
#include <cstddef>

typedef __half h16;

#define BDIM 16384
#define D1   1536
#define D2   3072
#define DH   512
#define DOUT 6

// ---------------- scratch (static device memory; no allocations) ----------------
static constexpr size_t SZ_X   = (size_t)BDIM * D1;
static constexpr size_t SZ_H   = (size_t)BDIM * DH;
static constexpr size_t SZ_WGE = (size_t)D1 * D1;
static constexpr size_t SZ_WGI = (size_t)D2 * D1;
static constexpr size_t SZ_W1  = (size_t)D1 * DH;
static constexpr size_t SZ_W2  = (size_t)DH * DH;

static constexpr size_t O_X   = 0;
static constexpr size_t O_GE  = O_X  + SZ_X;
static constexpr size_t O_GI  = O_GE + SZ_X;
static constexpr size_t O_H1  = O_GI + SZ_X;
static constexpr size_t O_H2  = O_H1 + SZ_H;
static constexpr size_t O_WGE = O_H2 + SZ_H;
static constexpr size_t O_WGI = O_WGE + SZ_WGE;
static constexpr size_t O_W1  = O_WGI + SZ_WGI;
static constexpr size_t O_W2  = O_W1 + SZ_W1;
static constexpr size_t SCRATCH_TOTAL = O_W2 + SZ_W2;

__device__ __align__(1024) h16 g_scratch[SCRATCH_TOTAL];

// ---------------- ptx helpers ----------------
__device__ __forceinline__ uint32_t smem_u32(const void* p) {
    uint32_t a;
    asm("{ .reg .u64 t; cvta.to.shared.u64 t, %1; cvt.u32.u64 %0, t; }" : "=r"(a) : "l"(p));
    return a;
}

__device__ __forceinline__ void cp16(uint32_t dst, const void* src) {
    asm volatile("cp.async.cg.shared.global [%0], [%1], 16;" :: "r"(dst), "l"(src) : "memory");
}

__device__ __forceinline__ void ldmx4(uint32_t* r, uint32_t addr) {
    asm volatile("ldmatrix.sync.aligned.m8n8.x4.shared.b16 {%0,%1,%2,%3}, [%4];"
        : "=r"(r[0]), "=r"(r[1]), "=r"(r[2]), "=r"(r[3]) : "r"(addr));
}

__device__ __forceinline__ void mma16816(float* c, const uint32_t* a, const uint32_t* b) {
    asm volatile(
        "mma.sync.aligned.m16n8k16.row.col.f32.f16.f16.f32 "
        "{%0,%1,%2,%3},{%4,%5,%6,%7},{%8,%9},{%0,%1,%2,%3};\n"
        : "+f"(c[0]), "+f"(c[1]), "+f"(c[2]), "+f"(c[3])
        : "r"(a[0]), "r"(a[1]), "r"(a[2]), "r"(a[3]),
          "r"(b[0]), "r"(b[1]));
}

// ---------------- prep kernels ----------------
// fp32 -> fp16, 8 floats per thread: 2x LDG.128 -> 1x STG.128
__global__ void cvt_kernel8(const float4* __restrict__ src,
                            uint4* __restrict__ dst, size_t n8) {
    size_t stride = (size_t)gridDim.x * blockDim.x;
    for (size_t i = (size_t)blockIdx.x * blockDim.x + threadIdx.x; i < n8; i += stride) {
        float4 a = src[2 * i];
        float4 b = src[2 * i + 1];
        __half2 h0 = __floats2half2_rn(a.x, a.y);
        __half2 h1 = __floats2half2_rn(a.z, a.w);
        __half2 h2 = __floats2half2_rn(b.x, b.y);
        __half2 h3 = __floats2half2_rn(b.z, b.w);
        uint4 o;
        o.x = *(uint32_t*)&h0; o.y = *(uint32_t*)&h1;
        o.z = *(uint32_t*)&h2; o.w = *(uint32_t*)&h3;
        dst[i] = o;
    }
}

// tiled transpose + optional mask + fp16: w [K][N] -> t [N][K]; mask [N][K].
// Write phase: each thread emits half2 (two consecutive k) -> 4B coalesced stores.
template<bool MASKED>
__global__ void prep_T(const float* __restrict__ w, const float* __restrict__ mask,
                       h16* __restrict__ t, int Kd, int Nd) {
    __shared__ float tl[32][33];
    const int k0 = blockIdx.x * 32, n0 = blockIdx.y * 32;
    const int tx = threadIdx.x, ty = threadIdx.y;  // 32 x 8
#pragma unroll
    for (int i = 0; i < 32; i += 8)
        tl[ty + i][tx] = w[(size_t)(k0 + ty + i) * Nd + (n0 + tx)];
    __syncthreads();
    // remap 256 threads: wtx 0..15 selects k-pair, wty 0..15 selects n row
    const int tid = ty * 32 + tx;
    const int wtx = tid & 15;        // k pair index
    const int wty = tid >> 4;        // 0..15
#pragma unroll
    for (int h = 0; h < 2; h++) {
        const int n = n0 + wty + h * 16;
        const int k = k0 + 2 * wtx;
        float v0 = tl[2 * wtx][wty + h * 16];
        float v1 = tl[2 * wtx + 1][wty + h * 16];
        const size_t idx = (size_t)n * Kd + k;
        if (MASKED) {
            float2 m = *(const float2*)&mask[idx];
            v0 *= m.x; v1 *= m.y;
        }
        *(__half2*)&t[idx] = __floats2half2_rn(v0, v1);
    }
}

// ---------------- mma.sync GEMM: C = A * B^T(+concat) + bias (opt relu), fp16 ----------------
// R11 EXACT config: CTA 128x128, BK=64 (128B swizzled rows), 3-stage cp.async
// (1 barrier/stage), 2 CTAs/SM, warp tile 64x32, interleaved fully-unrolled loader.
#define BM 128
#define BN 128
#define ABYTES (BM * 128)
#define BBYTES (BN * 128)
#define STAGEB (ABYTES + BBYTES)
#define SMEM_BYTES (3 * STAGEB)

template<bool RELU, bool CONCAT>
__global__ __launch_bounds__(256, 2)
void gemm_hmma(const h16* __restrict__ A, const h16* __restrict__ A2,
               int ksplit,
               const h16* __restrict__ Bt,  // [N][K]
               const float* __restrict__ bias,
               h16* __restrict__ O,
               int N, int K)
{
    constexpr int NI = 4;    // 64/16 M-frags
    constexpr int NJ = 4;    // 32/8  N-frags
    constexpr int NJP = 2;   // 32/16 N-frag pairs

    extern __shared__ __align__(1024) char smem[];
    const uint32_t sb = smem_u32(smem);

    const int tid  = threadIdx.x;
    const int lane = tid & 31;
    const int warp = tid >> 5;       // 0..7
    const int wm = warp >> 2;        // 0..1 (64-row slab)
    const int wn = warp & 3;         // 0..3 (32-col slab)
    const int blockN = blockIdx.x * BN;
    const int blockM = blockIdx.y * BM;

    // ldmatrix lane decomposition
    const int q = lane >> 3;
    const int m8 = lane & 7;
    const int qrA = q & 1;
    const int qcA = q >> 1;
    const int qrB = q >> 1;
    const int qcB = q & 1;

    uint32_t rA[NI], xA[NI];
#pragma unroll
    for (int i = 0; i < NI; i++) {
        int row = wm * 64 + i * 16 + qrA * 8 + m8;
        rA[i] = (uint32_t)row * 128u;
        xA[i] = (uint32_t)(row & 7);
    }
    uint32_t rB[NJP], xB[NJP];
#pragma unroll
    for (int jp = 0; jp < NJP; jp++) {
        int row = wn * 32 + jp * 16 + qrB * 8 + m8;
        rB[jp] = (uint32_t)row * 128u;
        xB[jp] = (uint32_t)(row & 7);
    }

    float acc[NI][NJ][4];
#pragma unroll
    for (int i = 0; i < NI; i++)
#pragma unroll
        for (int j = 0; j < NJ; j++)
#pragma unroll
            for (int r = 0; r < 4; r++) acc[i][j][r] = 0.f;

    const int S = K / 64;

    // ---- stage loader: A = 1024 16B-chunks, B = 1024 chunks; 256 threads
    // (interleaved, fully unrolled -- R11 codegen)
    auto do_load = [&](int s) {
        const int k0 = s * 64;
        const h16* a;
        size_t lda;
        if (CONCAT && k0 >= ksplit) {
            lda = (size_t)(K - ksplit);
            a = A2 + (size_t)blockM * lda + (k0 - ksplit);
        } else {
            lda = CONCAT ? (size_t)ksplit : (size_t)K;
            a = A + (size_t)blockM * lda + k0;
        }
        const h16* b = Bt + (size_t)blockN * K + k0;
        const uint32_t buf = sb + (uint32_t)(s % 3) * STAGEB;
#pragma unroll
        for (int it = 0; it < 4; it++) {
            const int chunk = it * 256 + tid;   // 0..1023
            const int row = chunk >> 3;
            const int col = chunk & 7;
            const uint32_t soff = (uint32_t)row * 128u + (uint32_t)((col ^ (row & 7)) * 16);
            cp16(buf + soff,          (const char*)(a + (size_t)row * lda) + col * 16);
            cp16(buf + ABYTES + soff, (const char*)(b + (size_t)row * K) + col * 16);
        }
    };

    do_load(0);
    asm volatile("cp.async.commit_group;" ::: "memory");
    if (S > 1) {
        do_load(1);
        asm volatile("cp.async.commit_group;" ::: "memory");
    }

    for (int s = 0; s < S; s++) {
        if (s < S - 1) asm volatile("cp.async.wait_group 1;" ::: "memory");
        else           asm volatile("cp.async.wait_group 0;" ::: "memory");
        __syncthreads();   // single barrier per stage (3-stage ring)

        if (s + 2 < S) {
            do_load(s + 2);
            asm volatile("cp.async.commit_group;" ::: "memory");
        }

        const uint32_t buf = sb + (uint32_t)(s % 3) * STAGEB;
        const uint32_t bA = buf;
        const uint32_t bB = buf + ABYTES;

#pragma unroll
        for (int ks = 0; ks < 4; ks++) {
            const uint32_t cA = (uint32_t)(ks * 2 + qcA);
            const uint32_t cB = (uint32_t)(ks * 2 + qcB);
            uint32_t af[NI][4], bf[NJP][4];
#pragma unroll
            for (int i = 0; i < NI; i++)
                ldmx4(af[i], bA + rA[i] + ((cA ^ xA[i]) << 4));
#pragma unroll
            for (int jp = 0; jp < NJP; jp++)
                ldmx4(bf[jp], bB + rB[jp] + ((cB ^ xB[jp]) << 4));
#pragma unroll
            for (int j = 0; j < NJ; j++)
#pragma unroll
                for (int i = 0; i < NI; i++)
                    mma16816(acc[i][j], af[i], &bf[j >> 1][(j & 1) * 2]);
        }
    }

    // ---- epilogue: bias, optional relu, fp16 store
    const int g  = lane >> 2;
    const int tg = lane & 3;
#pragma unroll
    for (int i = 0; i < NI; i++) {
#pragma unroll
        for (int j = 0; j < NJ; j++) {
            int row0 = blockM + wm * 64 + i * 16 + g;
            int col  = blockN + wn * 32 + j * 8 + tg * 2;
            float b0 = bias[col], b1 = bias[col + 1];
#pragma unroll
            for (int h = 0; h < 2; h++) {
                int row = row0 + h * 8;
                float v0 = acc[i][j][h * 2 + 0] + b0;
                float v1 = acc[i][j][h * 2 + 1] + b1;
                if (RELU) { v0 = fmaxf(v0, 0.f); v1 = fmaxf(v1, 0.f); }
                *(__half2*)&O[(size_t)row * N + col] = __floats2half2_rn(v0, v1);
            }
        }
    }
}

// ---------------- final layer: [B,512] x [512,6] + bias, relu (fp32) ----------------
__global__ void final_kernel(const h16* __restrict__ hh,
                             const float* __restrict__ w3, const float* __restrict__ b3,
                             float* __restrict__ out)
{
    int warpId = (int)((blockIdx.x * (size_t)blockDim.x + threadIdx.x) >> 5);
    int lane = threadIdx.x & 31;
    if (warpId >= BDIM) return;
    const h16* ph = hh + (size_t)warpId * DH;
    float acc[6] = {0.f, 0.f, 0.f, 0.f, 0.f, 0.f};
    for (int k = lane; k < DH; k += 32) {
        float h = __half2float(ph[k]);
#pragma unroll
        for (int n = 0; n < 6; n++) acc[n] += h * w3[k * 6 + n];
    }
#pragma unroll
    for (int n = 0; n < 6; n++)
#pragma unroll
        for (int off = 16; off; off >>= 1)
            acc[n] += __shfl_xor_sync(0xffffffffu, acc[n], off);
    if (lane == 0) {
#pragma unroll
        for (int n = 0; n < 6; n++)
            out[(size_t)warpId * 6 + n] = fmaxf(acc[n] + b3[n], 0.f);
    }
}

// ---------------- launch ----------------
extern "C" void kernel_launch(void* const* d_in, const int* in_sizes, int n_in,
                              void* d_out, int out_size)
{
    const float* x        = (const float*)d_in[0];
    const float* gpe_mask = (const float*)d_in[1];
    const float* gpe_w    = (const float*)d_in[2];
    const float* gpe_b    = (const float*)d_in[3];
    const float* gpi_mask = (const float*)d_in[4];
    const float* gpi_w    = (const float*)d_in[5];
    const float* gpi_b    = (const float*)d_in[6];
    const float* w1       = (const float*)d_in[7];
    const float* b1       = (const float*)d_in[8];
    const float* w2       = (const float*)d_in[9];
    const float* b2       = (const float*)d_in[10];
    const float* w3       = (const float*)d_in[11];
    const float* b3       = (const float*)d_in[12];
    float* out = (float*)d_out;

    h16* s = nullptr;
    cudaGetSymbolAddress((void**)&s, g_scratch);

    h16 *xc = s + O_X;
    h16 *ge = s + O_GE, *gi = s + O_GI;
    h16 *h1 = s + O_H1, *h2 = s + O_H2;
    h16 *wge = s + O_WGE, *wgi = s + O_WGI;
    h16 *w1c = s + O_W1, *w2c = s + O_W2;

    cudaFuncSetAttribute(gemm_hmma<false, false>, cudaFuncAttributeMaxDynamicSharedMemorySize, SMEM_BYTES);
    cudaFuncSetAttribute(gemm_hmma<false, true>,  cudaFuncAttributeMaxDynamicSharedMemorySize, SMEM_BYTES);
    cudaFuncSetAttribute(gemm_hmma<true,  false>, cudaFuncAttributeMaxDynamicSharedMemorySize, SMEM_BYTES);

    // Launch order keeps the ncu window (slots ~4-6) on big GEMMs.
    cvt_kernel8<<<4096, 256>>>((const float4*)x, (uint4*)xc, SZ_X / 8);
    prep_T<true><<<dim3(D1 / 32, D1 / 32), dim3(32, 8)>>>(gpe_w, gpe_mask, wge, D1, D1);
    prep_T<true><<<dim3(D2 / 32, D1 / 32), dim3(32, 8)>>>(gpi_w, gpi_mask, wgi, D2, D1);
    // layer 1: gpe = x @ Wgpe + b        [B,1536] x [1536,1536]
    gemm_hmma<false, false><<<dim3(D1 / BN, BDIM / BM), 256, SMEM_BYTES>>>(
        xc, nullptr, D1, wge, gpe_b, ge, D1, D1);
    // layer 2: gpi = [x, gpe] @ Wgpi + b [B,3072] x [3072,1536] (concat fused)
    gemm_hmma<false, true><<<dim3(D1 / BN, BDIM / BM), 256, SMEM_BYTES>>>(
        xc, ge, D1, wgi, gpi_b, gi, D1, D2);
    prep_T<false><<<dim3(D1 / 32, DH / 32), dim3(32, 8)>>>(w1, nullptr, w1c, D1, DH);
    prep_T<false><<<dim3(DH / 32, DH / 32), dim3(32, 8)>>>(w2, nullptr, w2c, DH, DH);
    // layer 3: h1 = relu(gpi @ w1 + b1)  [B,1536] x [1536,512]
    gemm_hmma<true, false><<<dim3(DH / BN, BDIM / BM), 256, SMEM_BYTES>>>(
        gi, nullptr, D1, w1c, b1, h1, DH, D1);
    // layer 4: h2 = relu(h1 @ w2 + b2)   [B,512] x [512,512]
    gemm_hmma<true, false><<<dim3(DH / BN, BDIM / BM), 256, SMEM_BYTES>>>(
        h1, nullptr, DH, w2c, b2, h2, DH, DH);
    // layer 5: out = relu(h2 @ w3 + b3)  [B,512] x [512,6]
    final_kernel<<<(BDIM * 32) / 256, 256>>>(h2, w3, b3, out);
}